// round 1
// baseline (speedup 1.0000x reference)
#include <cuda_runtime.h>

#define Hh 768
#define Ss 128
#define Bb_ 8
#define Pp 8256            // S*(S+1)/2
#define NROWS 1024         // B*S
#define H4 192             // H/4

__device__ __align__(16) float g_A1[NROWS * Hh];
__device__ __align__(16) float g_A2[NROWS * Hh];
__device__ __align__(16) float g_Bb[NROWS * Hh];
__device__ __align__(16) float g_Gg[NROWS * Hh];
__device__ float g_mean[NROWS];
__device__ float g_rstd[NROWS];

// C[m,n] = sum_k A[m*lda+k] * W[n*ldw+k] + bias[n]
// M=1024, N=768 fixed multiples of 64; K multiple of 16. C is row-major ldc=768.
__global__ void __launch_bounds__(256) gemm_nt(
    const float* __restrict__ A, int lda,
    const float* __restrict__ W, int ldw,
    const float* __restrict__ bias,
    float* __restrict__ C, int K)
{
    __shared__ __align__(16) float As[64][17];
    __shared__ __align__(16) float Wt[16][68];

    const int tid = threadIdx.x;
    const int tx = tid & 15;
    const int ty = tid >> 4;
    const int bm = blockIdx.y * 64;
    const int bn = blockIdx.x * 64;
    const int r  = tid >> 2;          // 0..63
    const int kq = (tid & 3) * 4;     // 0,4,8,12

    float acc[4][4];
#pragma unroll
    for (int i = 0; i < 4; ++i)
#pragma unroll
        for (int j = 0; j < 4; ++j) acc[i][j] = 0.f;

    for (int k0 = 0; k0 < K; k0 += 16) {
        float4 av = *(const float4*)(A + (size_t)(bm + r) * lda + k0 + kq);
        float4 wv = *(const float4*)(W + (size_t)(bn + r) * ldw + k0 + kq);
        __syncthreads();
        As[r][kq + 0] = av.x; As[r][kq + 1] = av.y;
        As[r][kq + 2] = av.z; As[r][kq + 3] = av.w;
        Wt[kq + 0][r] = wv.x; Wt[kq + 1][r] = wv.y;
        Wt[kq + 2][r] = wv.z; Wt[kq + 3][r] = wv.w;
        __syncthreads();
#pragma unroll
        for (int k = 0; k < 16; ++k) {
            float4 w4 = *(const float4*)&Wt[k][tx * 4];
            float a0 = As[ty * 4 + 0][k];
            float a1 = As[ty * 4 + 1][k];
            float a2 = As[ty * 4 + 2][k];
            float a3 = As[ty * 4 + 3][k];
            acc[0][0] += a0 * w4.x; acc[0][1] += a0 * w4.y; acc[0][2] += a0 * w4.z; acc[0][3] += a0 * w4.w;
            acc[1][0] += a1 * w4.x; acc[1][1] += a1 * w4.y; acc[1][2] += a1 * w4.z; acc[1][3] += a1 * w4.w;
            acc[2][0] += a2 * w4.x; acc[2][1] += a2 * w4.y; acc[2][2] += a2 * w4.z; acc[2][3] += a2 * w4.w;
            acc[3][0] += a3 * w4.x; acc[3][1] += a3 * w4.y; acc[3][2] += a3 * w4.z; acc[3][3] += a3 * w4.w;
        }
    }

    const int row0 = bm + ty * 4;
    const int col0 = bn + tx * 4;
    float4 bv = make_float4(0.f, 0.f, 0.f, 0.f);
    if (bias) bv = *(const float4*)(bias + col0);
#pragma unroll
    for (int i = 0; i < 4; ++i) {
        float4 o;
        o.x = acc[i][0] + bv.x; o.y = acc[i][1] + bv.y;
        o.z = acc[i][2] + bv.z; o.w = acc[i][3] + bv.w;
        *(float4*)(C + (size_t)(row0 + i) * Hh + col0) = o;
    }
}

// Per-row mean / rstd of Y rows. Two-pass to match reference numerics.
__global__ void __launch_bounds__(256) stats_kernel(const float* __restrict__ Y)
{
    const int row = blockIdx.x;
    const float* p = Y + (size_t)row * Hh;
    const int tid = threadIdx.x;
    __shared__ float red[8];
    __shared__ float red2[8];
    __shared__ float s_mean;

    float s = 0.f;
    for (int k = tid; k < Hh; k += 256) s += p[k];
#pragma unroll
    for (int o = 16; o; o >>= 1) s += __shfl_down_sync(0xffffffffu, s, o);
    if ((tid & 31) == 0) red[tid >> 5] = s;
    __syncthreads();
    if (tid == 0) {
        float v = 0.f;
#pragma unroll
        for (int w = 0; w < 8; ++w) v += red[w];
        s_mean = v * (1.0f / Hh);
    }
    __syncthreads();
    const float m = s_mean;

    float ss = 0.f;
    for (int k = tid; k < Hh; k += 256) { float d = p[k] - m; ss += d * d; }
#pragma unroll
    for (int o = 16; o; o >>= 1) ss += __shfl_down_sync(0xffffffffu, ss, o);
    if ((tid & 31) == 0) red2[tid >> 5] = ss;
    __syncthreads();
    if (tid == 0) {
        float v = 0.f;
#pragma unroll
        for (int w = 0; w < 8; ++w) v += red2[w];
        float var = v * (1.0f / Hh);
        float sd = var + 1e-12f;
        sd = sd * sd;                 // reference: std = (var+eps)**2
        g_mean[row] = m;
        g_rstd[row] = 1.0f / sd;
    }
}

// One block per (i, b). Hoist A1/Bb/Gg row for (b,i) to registers, stream j.
__global__ void __launch_bounds__(192) epilogue_kernel(
    const float4* __restrict__ Y4, float4* __restrict__ out)
{
    const int i = blockIdx.x;
    const int b = blockIdx.y;
    const int c = threadIdx.x;          // 0..191 (float4 lane of H)

    const float4* A1 = (const float4*)g_A1;
    const float4* A2 = (const float4*)g_A2;
    const float4* Bv = (const float4*)g_Bb;
    const float4* Gv = (const float4*)g_Gg;

    const int rx = b * Ss + i;
    const float4 a1 = A1[(size_t)rx * H4 + c];
    const float4 bb = Bv[(size_t)rx * H4 + c];
    const float4 gg = Gv[(size_t)rx * H4 + c];

    // output row for (b,i,j) = b*P + i*S - i*(i-1)/2 + (j - i)
    const long pbase = (long)b * Pp + (long)i * Ss - ((long)i * (i - 1)) / 2 - i;

    for (int j = i; j < Ss; ++j) {
        const int ry = b * Ss + j;
        float4 a2 = A2[(size_t)ry * H4 + c];
        float4 yv = Y4[(size_t)ry * H4 + c];
        float m  = g_mean[ry];
        float rr = g_rstd[ry];
        float4 o;
        o.x = 0.5f * (fmaxf(a1.x + a2.x, 0.f) + (yv.x - m) * rr * gg.x + bb.x);
        o.y = 0.5f * (fmaxf(a1.y + a2.y, 0.f) + (yv.y - m) * rr * gg.y + bb.y);
        o.z = 0.5f * (fmaxf(a1.z + a2.z, 0.f) + (yv.z - m) * rr * gg.z + bb.z);
        o.w = 0.5f * (fmaxf(a1.w + a2.w, 0.f) + (yv.w - m) * rr * gg.w + bb.w);
        __stcs(&out[(size_t)(pbase + j) * H4 + c], o);
    }
}

extern "C" void kernel_launch(void* const* d_in, const int* in_sizes, int n_in,
                              void* d_out, int out_size)
{
    const float* x      = (const float*)d_in[0];   // (B,S,H)
    const float* y      = (const float*)d_in[1];   // (B,S,H)
    const float* cat_W  = (const float*)d_in[2];   // (H, 2H)
    const float* cat_b  = (const float*)d_in[3];   // (H,)
    const float* beta   = (const float*)d_in[4];   // (H,)
    const float* gamma  = (const float*)d_in[5];   // (H,)
    const float* beta_W = (const float*)d_in[6];   // (H,H)
    const float* gammaW = (const float*)d_in[7];   // (H,H)
    float* out = (float*)d_out;

    float* A1; cudaGetSymbolAddress((void**)&A1, g_A1);
    float* A2; cudaGetSymbolAddress((void**)&A2, g_A2);
    float* Bp; cudaGetSymbolAddress((void**)&Bp, g_Bb);
    float* Gp; cudaGetSymbolAddress((void**)&Gp, g_Gg);

    dim3 gblk(256);
    dim3 ggrid(Hh / 64, NROWS / 64);   // (12, 16)

    // A1 = X * Wg^T + cat_b   (Wg = cat_W[:, :H], row stride 2H)
    gemm_nt<<<ggrid, gblk>>>(x, Hh, cat_W, 2 * Hh, cat_b, A1, Hh);
    // A2 = Y * Wv^T           (Wv = cat_W[:, H:], row stride 2H)
    gemm_nt<<<ggrid, gblk>>>(y, Hh, cat_W + Hh, 2 * Hh, nullptr, A2, Hh);
    // Bb = X * beta_W^T + beta
    gemm_nt<<<ggrid, gblk>>>(x, Hh, beta_W, Hh, beta, Bp, Hh);
    // Gg = X * gamma_W^T + gamma
    gemm_nt<<<ggrid, gblk>>>(x, Hh, gammaW, Hh, gamma, Gp, Hh);
    // per-row mean / rstd of Y
    stats_kernel<<<NROWS, 256>>>(y);
    // fused epilogue over all (b, i, j>=i)
    dim3 egrid(Ss, Bb_);
    epilogue_kernel<<<egrid, 192>>>((const float4*)y, (float4*)out);
}

// round 2
// speedup vs baseline: 1.5378x; 1.5378x over previous
#include <cuda_runtime.h>

#define Hh 768
#define Ss 128
#define Bb_ 8
#define Pp 8256            // S*(S+1)/2
#define NROWS 1024         // B*S
#define H4 192             // H/4
#define NTOT 3072          // combined N: A1|A2|Bb|Gg

__device__ __align__(16) float g_part0[NROWS * NTOT];
__device__ __align__(16) float g_part1[NROWS * NTOT];
__device__ __align__(16) float g_A1[NROWS * Hh];
__device__ __align__(16) float g_A2[NROWS * Hh];
__device__ __align__(16) float g_Bb[NROWS * Hh];
__device__ __align__(16) float g_Gg[NROWS * Hh];
__device__ float g_mean[NROWS];
__device__ float g_rstd[NROWS];

// Fused K-split SGEMM. grid = (24 n-tiles, 8 m-tiles, 2 k-halves), 256 thr.
// Tile 128x128, per-thread 8x8 via 4+4 split layout. Partials to g_part{0,1}.
__global__ void __launch_bounds__(256, 2) gemm_ksplit(
    const float* __restrict__ X, const float* __restrict__ Y,
    const float* __restrict__ catW,
    const float* __restrict__ betaW, const float* __restrict__ gammaW)
{
    __shared__ __align__(16) float As[2][8][132];
    __shared__ __align__(16) float Bs[2][8][132];

    const int nt = blockIdx.x;          // 0..23
    const int bm = blockIdx.y * 128;    // m tile base
    const int kz = blockIdx.z;          // 0/1
    const int kb = kz * 384;

    const float* A; const float* W; int ldw;
    const int grp = nt / 6;
    const int bn  = (nt % 6) * 128;
    if (grp == 0)      { A = X; W = catW;       ldw = 2 * Hh; }
    else if (grp == 1) { A = Y; W = catW + Hh;  ldw = 2 * Hh; }
    else if (grp == 2) { A = X; W = betaW;      ldw = Hh;     }
    else               { A = X; W = gammaW;     ldw = Hh;     }

    const int tid = threadIdx.x;
    const int lm = tid >> 1;            // 0..127 (row within tile for loads)
    const int lk = (tid & 1) * 4;       // 0 or 4
    const int tm4 = (tid >> 4) * 4;     // compute row group
    const int tn4 = (tid & 15) * 4;     // compute col group

    const float* Aload = A + (size_t)(bm + lm) * Hh + kb + lk;
    const float* Wload = W + (size_t)(bn + lm) * ldw + kb + lk;

    float acc[8][8];
#pragma unroll
    for (int i = 0; i < 8; ++i)
#pragma unroll
        for (int j = 0; j < 8; ++j) acc[i][j] = 0.f;

    float4 av = *(const float4*)Aload;
    float4 wv = *(const float4*)Wload;
    As[0][lk+0][lm] = av.x; As[0][lk+1][lm] = av.y;
    As[0][lk+2][lm] = av.z; As[0][lk+3][lm] = av.w;
    Bs[0][lk+0][lm] = wv.x; Bs[0][lk+1][lm] = wv.y;
    Bs[0][lk+2][lm] = wv.z; Bs[0][lk+3][lm] = wv.w;
    __syncthreads();

    const int NIT = 48;                 // 384 / 8
    for (int it = 0; it < NIT; ++it) {
        const int cur = it & 1;
        if (it + 1 < NIT) {
            av = *(const float4*)(Aload + (it + 1) * 8);
            wv = *(const float4*)(Wload + (it + 1) * 8);
        }
#pragma unroll
        for (int k = 0; k < 8; ++k) {
            float4 a0 = *(const float4*)&As[cur][k][tm4];
            float4 a1 = *(const float4*)&As[cur][k][tm4 + 64];
            float4 b0 = *(const float4*)&Bs[cur][k][tn4];
            float4 b1 = *(const float4*)&Bs[cur][k][tn4 + 64];
            float a[8] = {a0.x,a0.y,a0.z,a0.w,a1.x,a1.y,a1.z,a1.w};
            float b[8] = {b0.x,b0.y,b0.z,b0.w,b1.x,b1.y,b1.z,b1.w};
#pragma unroll
            for (int i = 0; i < 8; ++i)
#pragma unroll
                for (int j = 0; j < 8; ++j)
                    acc[i][j] = fmaf(a[i], b[j], acc[i][j]);
        }
        if (it + 1 < NIT) {
            const int nxt = cur ^ 1;
            As[nxt][lk+0][lm] = av.x; As[nxt][lk+1][lm] = av.y;
            As[nxt][lk+2][lm] = av.z; As[nxt][lk+3][lm] = av.w;
            Bs[nxt][lk+0][lm] = wv.x; Bs[nxt][lk+1][lm] = wv.y;
            Bs[nxt][lk+2][lm] = wv.z; Bs[nxt][lk+3][lm] = wv.w;
            __syncthreads();
        }
    }

    float* P = kz ? g_part1 : g_part0;
#pragma unroll
    for (int hi = 0; hi < 2; ++hi)
#pragma unroll
        for (int ii = 0; ii < 4; ++ii) {
            const int i = hi * 4 + ii;
            float* row = P + (size_t)(bm + hi * 64 + tm4 + ii) * NTOT + nt * 128;
            *(float4*)(row + tn4)      = make_float4(acc[i][0], acc[i][1], acc[i][2], acc[i][3]);
            *(float4*)(row + 64 + tn4) = make_float4(acc[i][4], acc[i][5], acc[i][6], acc[i][7]);
        }
}

// part0 + part1 + bias -> the 4 activation arrays. float4 granularity.
__global__ void __launch_bounds__(256) reduce_bias(
    const float* __restrict__ catb, const float* __restrict__ beta,
    const float* __restrict__ gamma)
{
    const int idx = blockIdx.x * 256 + threadIdx.x;   // over 1024*768 float4s
    const int m  = idx / (NTOT / 4);
    const int c4 = idx % (NTOT / 4);
    const int g  = c4 / H4;
    const int l4 = c4 % H4;

    float4 p = ((const float4*)g_part0)[idx];
    float4 q = ((const float4*)g_part1)[idx];
    float4 o;
    o.x = p.x + q.x; o.y = p.y + q.y; o.z = p.z + q.z; o.w = p.w + q.w;

    if (g == 0) {
        float4 bv = *(const float4*)(catb + l4 * 4);
        o.x += bv.x; o.y += bv.y; o.z += bv.z; o.w += bv.w;
        ((float4*)g_A1)[m * H4 + l4] = o;
    } else if (g == 1) {
        ((float4*)g_A2)[m * H4 + l4] = o;
    } else if (g == 2) {
        float4 bv = *(const float4*)(beta + l4 * 4);
        o.x += bv.x; o.y += bv.y; o.z += bv.z; o.w += bv.w;
        ((float4*)g_Bb)[m * H4 + l4] = o;
    } else {
        float4 bv = *(const float4*)(gamma + l4 * 4);
        o.x += bv.x; o.y += bv.y; o.z += bv.z; o.w += bv.w;
        ((float4*)g_Gg)[m * H4 + l4] = o;
    }
}

// Per-row mean / rstd of Y rows. Two-pass to match reference numerics.
__global__ void __launch_bounds__(256) stats_kernel(const float* __restrict__ Y)
{
    const int row = blockIdx.x;
    const float* p = Y + (size_t)row * Hh;
    const int tid = threadIdx.x;
    __shared__ float red[8];
    __shared__ float red2[8];
    __shared__ float s_mean;

    float s = 0.f;
    for (int k = tid; k < Hh; k += 256) s += p[k];
#pragma unroll
    for (int o = 16; o; o >>= 1) s += __shfl_down_sync(0xffffffffu, s, o);
    if ((tid & 31) == 0) red[tid >> 5] = s;
    __syncthreads();
    if (tid == 0) {
        float v = 0.f;
#pragma unroll
        for (int w = 0; w < 8; ++w) v += red[w];
        s_mean = v * (1.0f / Hh);
    }
    __syncthreads();
    const float m = s_mean;

    float ss = 0.f;
    for (int k = tid; k < Hh; k += 256) { float d = p[k] - m; ss += d * d; }
#pragma unroll
    for (int o = 16; o; o >>= 1) ss += __shfl_down_sync(0xffffffffu, ss, o);
    if ((tid & 31) == 0) red2[tid >> 5] = ss;
    __syncthreads();
    if (tid == 0) {
        float v = 0.f;
#pragma unroll
        for (int w = 0; w < 8; ++w) v += red2[w];
        float var = v * (1.0f / Hh);
        float sd = var + 1e-12f;
        sd = sd * sd;                 // reference: std = (var+eps)**2
        g_mean[row] = m;
        g_rstd[row] = 1.0f / sd;
    }
}

// Balanced epilogue: block q handles i=q and i=127-q (129 rows each).
__global__ void __launch_bounds__(192) epilogue_kernel(
    const float4* __restrict__ Y4, float4* __restrict__ out)
{
    const int q = blockIdx.x;           // 0..63
    const int b = blockIdx.y;
    const int c = threadIdx.x;          // float4 lane of H

    const float4* A1 = (const float4*)g_A1;
    const float4* A2 = (const float4*)g_A2;
    const float4* Bv = (const float4*)g_Bb;
    const float4* Gv = (const float4*)g_Gg;

#pragma unroll
    for (int t = 0; t < 2; ++t) {
        const int i = t ? (Ss - 1 - q) : q;
        const int rx = b * Ss + i;
        const float4 a1 = A1[(size_t)rx * H4 + c];
        const float4 bb = Bv[(size_t)rx * H4 + c];
        const float4 gg = Gv[(size_t)rx * H4 + c];

        const long pbase = (long)b * Pp + (long)i * Ss - ((long)i * (i - 1)) / 2 - i;

        for (int j = i; j < Ss; ++j) {
            const int ry = b * Ss + j;
            float4 a2 = A2[(size_t)ry * H4 + c];
            float4 yv = Y4[(size_t)ry * H4 + c];
            float m  = g_mean[ry];
            float rr = g_rstd[ry];
            float4 o;
            o.x = 0.5f * (fmaxf(a1.x + a2.x, 0.f) + (yv.x - m) * rr * gg.x + bb.x);
            o.y = 0.5f * (fmaxf(a1.y + a2.y, 0.f) + (yv.y - m) * rr * gg.y + bb.y);
            o.z = 0.5f * (fmaxf(a1.z + a2.z, 0.f) + (yv.z - m) * rr * gg.z + bb.z);
            o.w = 0.5f * (fmaxf(a1.w + a2.w, 0.f) + (yv.w - m) * rr * gg.w + bb.w);
            __stcs(&out[(size_t)(pbase + j) * H4 + c], o);
        }
    }
}

extern "C" void kernel_launch(void* const* d_in, const int* in_sizes, int n_in,
                              void* d_out, int out_size)
{
    const float* x      = (const float*)d_in[0];   // (B,S,H)
    const float* y      = (const float*)d_in[1];   // (B,S,H)
    const float* cat_W  = (const float*)d_in[2];   // (H, 2H)
    const float* cat_b  = (const float*)d_in[3];   // (H,)
    const float* beta   = (const float*)d_in[4];   // (H,)
    const float* gamma  = (const float*)d_in[5];   // (H,)
    const float* beta_W = (const float*)d_in[6];   // (H,H)
    const float* gammaW = (const float*)d_in[7];   // (H,H)
    float* out = (float*)d_out;

    // stats first (independent of GEMMs)
    stats_kernel<<<NROWS, 256>>>(y);

    dim3 ggrid(24, 8, 2);
    gemm_ksplit<<<ggrid, 256>>>(x, y, cat_W, beta_W, gammaW);

    reduce_bias<<<(NROWS * NTOT / 4) / 256, 256>>>(cat_b, beta, gamma);

    dim3 egrid(Ss / 2, Bb_);
    epilogue_kernel<<<egrid, 192>>>((const float4*)y, (float4*)out);
}

// round 3
// speedup vs baseline: 2.3831x; 1.5496x over previous
#include <cuda_runtime.h>
#include <cuda_bf16.h>
#include <cstdint>

#define Hh 768
#define Ss 128
#define Bb_ 8
#define Pp 8256            // S*(S+1)/2
#define NROWS 1024         // B*S
#define H4 192             // H/4
#define PITCH 24           // bf16 elems per smem row (k-chunk 16 + pad 8)

__device__ __align__(16) float g_A1[NROWS * Hh];
__device__ __align__(16) float g_A2[NROWS * Hh];
__device__ __align__(16) float g_Bb[NROWS * Hh];
__device__ __align__(16) float g_Gg[NROWS * Hh];
__device__ __align__(16) float g_Z[NROWS * Hh];   // (y - mean) * rstd

#define LDSM4(R, addr) \
    asm volatile("ldmatrix.sync.aligned.m8n8.x4.shared.b16 {%0,%1,%2,%3}, [%4];" \
        : "=r"((R)[0]), "=r"((R)[1]), "=r"((R)[2]), "=r"((R)[3]) : "r"(addr))

#define MMA16816(c, a, b0, b1) \
    asm volatile("mma.sync.aligned.m16n8k16.row.col.f32.bf16.bf16.f32 " \
        "{%0,%1,%2,%3},{%4,%5,%6,%7},{%8,%9},{%0,%1,%2,%3};" \
        : "+f"((c)[0]), "+f"((c)[1]), "+f"((c)[2]), "+f"((c)[3]) \
        : "r"((a)[0]), "r"((a)[1]), "r"((a)[2]), "r"((a)[3]), "r"(b0), "r"(b1))

// split float4 -> hi/lo bf16x2 pairs, store 8B each to smem
__device__ __forceinline__ void split_sts(float4 v, __nv_bfloat16* hb, __nv_bfloat16* lb, int off)
{
    __nv_bfloat162 h0 = __float22bfloat162_rn(make_float2(v.x, v.y));
    __nv_bfloat162 h1 = __float22bfloat162_rn(make_float2(v.z, v.w));
    float2 f0 = __bfloat1622float2(h0);
    float2 f1 = __bfloat1622float2(h1);
    __nv_bfloat162 l0 = __float22bfloat162_rn(make_float2(v.x - f0.x, v.y - f0.y));
    __nv_bfloat162 l1 = __float22bfloat162_rn(make_float2(v.z - f1.x, v.w - f1.y));
    uint2 hv, lv;
    hv.x = *(uint32_t*)&h0; hv.y = *(uint32_t*)&h1;
    lv.x = *(uint32_t*)&l0; lv.y = *(uint32_t*)&l1;
    *(uint2*)(hb + off) = hv;
    *(uint2*)(lb + off) = lv;
}

// Fused tensor-core GEMM: C[1024 x 3072] in 4 groups of 768 cols.
// Block tile 64x128, K=768 in 48 chunks of 16. 256 threads = 8 warps (2x4),
// warp tile 32x32 = 2 m16 x 4 n8 mma tiles. bf16 hi/lo split, 3 mma terms.
__global__ void __launch_bounds__(256, 2) gemm_bf16split(
    const float* __restrict__ X, const float* __restrict__ Y,
    const float* __restrict__ catW, const float* __restrict__ catb,
    const float* __restrict__ beta, const float* __restrict__ gamma,
    const float* __restrict__ betaW, const float* __restrict__ gammaW)
{
    __shared__ __align__(16) __nv_bfloat16 sAh[2][64 * PITCH];
    __shared__ __align__(16) __nv_bfloat16 sAl[2][64 * PITCH];
    __shared__ __align__(16) __nv_bfloat16 sWh[2][128 * PITCH];
    __shared__ __align__(16) __nv_bfloat16 sWl[2][128 * PITCH];

    const int nt = blockIdx.x;          // 0..23
    const int bm = blockIdx.y * 64;
    const int grp = nt / 6;
    const int bn = (nt % 6) * 128;

    const float* A; const float* W; int ldw;
    if (grp == 0)      { A = X; W = catW;       ldw = 2 * Hh; }
    else if (grp == 1) { A = Y; W = catW + Hh;  ldw = 2 * Hh; }
    else if (grp == 2) { A = X; W = betaW;      ldw = Hh;     }
    else               { A = X; W = gammaW;     ldw = Hh;     }

    const int tid  = threadIdx.x;
    const int lane = tid & 31;
    const int warp = tid >> 5;
    const int wm = (warp >> 2) * 32;    // 0 / 32
    const int wn = (warp & 3) * 32;     // 0 / 32 / 64 / 96

    // gmem loader mapping: A 64x16 (1 float4/thr), W 128x16 (2 float4/thr)
    const int a_r = tid >> 2;
    const int a_c = (tid & 3) * 4;
    const float* Aptr  = A + (size_t)(bm + a_r) * Hh + a_c;
    const float* Wptr0 = W + (size_t)(bn + a_r) * ldw + a_c;
    const float* Wptr1 = Wptr0 + (size_t)64 * ldw;
    const int sAoff = a_r * PITCH + a_c;
    const int sWoff0 = a_r * PITCH + a_c;
    const int sWoff1 = (a_r + 64) * PITCH + a_c;

    // ldmatrix per-lane offsets (bytes)
    const uint32_t a_off = (uint32_t)(((wm + (lane & 15)) * PITCH + ((lane >> 4) * 8)) * 2);
    const uint32_t b_off = (uint32_t)(((wn + (lane & 7) + ((lane >> 4) << 3)) * PITCH
                                      + (((lane >> 3) & 1) * 8)) * 2);
    uint32_t baseAh[2], baseAl[2], baseWh[2], baseWl[2];
#pragma unroll
    for (int s = 0; s < 2; ++s) {
        baseAh[s] = (uint32_t)__cvta_generic_to_shared(&sAh[s][0]);
        baseAl[s] = (uint32_t)__cvta_generic_to_shared(&sAl[s][0]);
        baseWh[s] = (uint32_t)__cvta_generic_to_shared(&sWh[s][0]);
        baseWl[s] = (uint32_t)__cvta_generic_to_shared(&sWl[s][0]);
    }

    float c[2][4][4];
#pragma unroll
    for (int i = 0; i < 2; ++i)
#pragma unroll
        for (int j = 0; j < 4; ++j)
#pragma unroll
            for (int k = 0; k < 4; ++k) c[i][j][k] = 0.f;

    float4 av  = *(const float4*)Aptr;
    float4 wv0 = *(const float4*)Wptr0;
    float4 wv1 = *(const float4*)Wptr1;
    split_sts(av,  sAh[0], sAl[0], sAoff);
    split_sts(wv0, sWh[0], sWl[0], sWoff0);
    split_sts(wv1, sWh[0], sWl[0], sWoff1);
    __syncthreads();

    const int NIT = Hh / 16;   // 48
    for (int kc = 0; kc < NIT; ++kc) {
        const int cur = kc & 1;
        if (kc + 1 < NIT) {
            av  = *(const float4*)(Aptr  + (kc + 1) * 16);
            wv0 = *(const float4*)(Wptr0 + (kc + 1) * 16);
            wv1 = *(const float4*)(Wptr1 + (kc + 1) * 16);
        }

        uint32_t ah[2][4], al[2][4], bh[2][4], bl[2][4];
        LDSM4(ah[0], baseAh[cur] + a_off);
        LDSM4(ah[1], baseAh[cur] + a_off + 16 * PITCH * 2);
        LDSM4(al[0], baseAl[cur] + a_off);
        LDSM4(al[1], baseAl[cur] + a_off + 16 * PITCH * 2);
        LDSM4(bh[0], baseWh[cur] + b_off);
        LDSM4(bh[1], baseWh[cur] + b_off + 16 * PITCH * 2);
        LDSM4(bl[0], baseWl[cur] + b_off);
        LDSM4(bl[1], baseWl[cur] + b_off + 16 * PITCH * 2);

#pragma unroll
        for (int mt = 0; mt < 2; ++mt) {
#pragma unroll
            for (int ntl = 0; ntl < 4; ++ntl) {
                const int p = ntl >> 1;
                const int q = (ntl & 1) * 2;
                MMA16816(c[mt][ntl], ah[mt], bh[p][q], bh[p][q + 1]);
                MMA16816(c[mt][ntl], ah[mt], bl[p][q], bl[p][q + 1]);
                MMA16816(c[mt][ntl], al[mt], bh[p][q], bh[p][q + 1]);
            }
        }

        if (kc + 1 < NIT) {
            const int nxt = cur ^ 1;
            split_sts(av,  sAh[nxt], sAl[nxt], sAoff);
            split_sts(wv0, sWh[nxt], sWl[nxt], sWoff0);
            split_sts(wv1, sWh[nxt], sWl[nxt], sWoff1);
            __syncthreads();
        }
    }

    // epilogue: add bias, write to the target activation array
    float* OUT;
    const float* bias;
    if (grp == 0)      { OUT = g_A1; bias = catb;  }
    else if (grp == 1) { OUT = g_A2; bias = nullptr; }
    else if (grp == 2) { OUT = g_Bb; bias = beta;  }
    else               { OUT = g_Gg; bias = gamma; }

    const int g  = lane >> 2;
    const int t2 = (lane & 3) * 2;
#pragma unroll
    for (int mt = 0; mt < 2; ++mt) {
#pragma unroll
        for (int ntl = 0; ntl < 4; ++ntl) {
            const int col  = bn + wn + ntl * 8 + t2;
            float2 bv = make_float2(0.f, 0.f);
            if (bias) bv = *(const float2*)(bias + col);
            const int row0 = bm + wm + mt * 16 + g;
            float2 o0, o1;
            o0.x = c[mt][ntl][0] + bv.x; o0.y = c[mt][ntl][1] + bv.y;
            o1.x = c[mt][ntl][2] + bv.x; o1.y = c[mt][ntl][3] + bv.y;
            *(float2*)(OUT + (size_t)row0 * Hh + col)       = o0;
            *(float2*)(OUT + (size_t)(row0 + 8) * Hh + col) = o1;
        }
    }
}

// Per-row mean/rstd of Y (two-pass), then write Z = (y - mean) * rstd.
__global__ void __launch_bounds__(256) stats_kernel(const float* __restrict__ Y)
{
    const int row = blockIdx.x;
    const float* p = Y + (size_t)row * Hh;
    const int tid = threadIdx.x;
    __shared__ float red[8];
    __shared__ float red2[8];
    __shared__ float s_mean, s_rstd;

    float s = 0.f;
    for (int k = tid; k < Hh; k += 256) s += p[k];
#pragma unroll
    for (int o = 16; o; o >>= 1) s += __shfl_down_sync(0xffffffffu, s, o);
    if ((tid & 31) == 0) red[tid >> 5] = s;
    __syncthreads();
    if (tid == 0) {
        float v = 0.f;
#pragma unroll
        for (int w = 0; w < 8; ++w) v += red[w];
        s_mean = v * (1.0f / Hh);
    }
    __syncthreads();
    const float m = s_mean;

    float ss = 0.f;
    for (int k = tid; k < Hh; k += 256) { float d = p[k] - m; ss += d * d; }
#pragma unroll
    for (int o = 16; o; o >>= 1) ss += __shfl_down_sync(0xffffffffu, ss, o);
    if ((tid & 31) == 0) red2[tid >> 5] = ss;
    __syncthreads();
    if (tid == 0) {
        float v = 0.f;
#pragma unroll
        for (int w = 0; w < 8; ++w) v += red2[w];
        float var = v * (1.0f / Hh);
        float sd = var + 1e-12f;
        sd = sd * sd;                  // reference: std = (var+eps)**2
        s_rstd = 1.0f / sd;
    }
    __syncthreads();
    const float rr = s_rstd;
    float* z = g_Z + (size_t)row * Hh;
    for (int k = tid; k < Hh; k += 256) z[k] = (p[k] - m) * rr;
}

// Epilogue: grid (4 j-chunks, 128 i, 8 b), block 192 (one float4 lane each).
__global__ void __launch_bounds__(192) epilogue_kernel(float4* __restrict__ out)
{
    const int ch = blockIdx.x;
    const int i  = blockIdx.y;
    const int b  = blockIdx.z;
    const int c  = threadIdx.x;

    int j0 = ch * 32; if (i > j0) j0 = i;
    const int j1 = ch * 32 + 32;
    if (j0 >= j1) return;

    const float4* A1 = (const float4*)g_A1;
    const float4* A2 = (const float4*)g_A2;
    const float4* Bv = (const float4*)g_Bb;
    const float4* Gv = (const float4*)g_Gg;
    const float4* Z4 = (const float4*)g_Z;

    const int rx = b * Ss + i;
    const float4 a1 = A1[(size_t)rx * H4 + c];
    const float4 bb = Bv[(size_t)rx * H4 + c];
    const float4 gg = Gv[(size_t)rx * H4 + c];

    // output row for (b,i,j) = b*P + i*S - i*(i-1)/2 + (j - i)
    const long pbase = (long)b * Pp + (long)i * Ss - ((long)i * (i - 1)) / 2 - i;

#pragma unroll 4
    for (int j = j0; j < j1; ++j) {
        const int ry = b * Ss + j;
        float4 a2 = A2[(size_t)ry * H4 + c];
        float4 zv = Z4[(size_t)ry * H4 + c];
        float4 o;
        o.x = 0.5f * (fmaxf(a1.x + a2.x, 0.f) + zv.x * gg.x + bb.x);
        o.y = 0.5f * (fmaxf(a1.y + a2.y, 0.f) + zv.y * gg.y + bb.y);
        o.z = 0.5f * (fmaxf(a1.z + a2.z, 0.f) + zv.z * gg.z + bb.z);
        o.w = 0.5f * (fmaxf(a1.w + a2.w, 0.f) + zv.w * gg.w + bb.w);
        __stcs(&out[(size_t)(pbase + j) * H4 + c], o);
    }
}

extern "C" void kernel_launch(void* const* d_in, const int* in_sizes, int n_in,
                              void* d_out, int out_size)
{
    const float* x      = (const float*)d_in[0];
    const float* y      = (const float*)d_in[1];
    const float* cat_W  = (const float*)d_in[2];
    const float* cat_b  = (const float*)d_in[3];
    const float* beta   = (const float*)d_in[4];
    const float* gamma  = (const float*)d_in[5];
    const float* beta_W = (const float*)d_in[6];
    const float* gammaW = (const float*)d_in[7];
    float* out = (float*)d_out;

    stats_kernel<<<NROWS, 256>>>(y);

    dim3 ggrid(24, 16);
    gemm_bf16split<<<ggrid, 256>>>(x, y, cat_W, cat_b, beta, gamma, beta_W, gammaW);

    dim3 egrid(4, Ss, Bb_);
    epilogue_kernel<<<egrid, 192>>>((float4*)out);
}